// round 12
// baseline (speedup 1.0000x reference)
#include <cuda_runtime.h>
#include <cuda_fp16.h>

#define NN   50000
#define DD   128
#define NV2  (NN * DD / 4)      // uint2 (4 halves) per T slot = 1.6M
#define NNZ_CAP 800000
#define MCAP 32

#define SCAN_BLK 256
#define NBLK ((NN + SCAN_BLK - 1) / SCAN_BLK)   // 196

// ---- static scratch (allocation-free rule: __device__ globals) ----
__device__ __half g_T[MCAP * NN * DD];   // all Chebyshev iterates, fp16 (slot k = T_k)
__device__ int   g_cnt[NN];
__device__ int   g_rptr[NN + 1];
__device__ int   g_cursor[NN];
__device__ int   g_blksum[NBLK];
__device__ int   g_blkoff[NBLK];
__device__ int2  g_edges[NNZ_CAP];       // {col, val-as-int}

// ---------------- CSR build (R10-proven 3-kernel scan) ----------------
__global__ void hist_kernel(const int* __restrict__ rows, int nnz) {
    int i = blockIdx.x * blockDim.x + threadIdx.x;
    if (i < nnz) atomicAdd(&g_cnt[rows[i]], 1);
}

__global__ void scan_blocks_kernel() {
    __shared__ int sh[SCAN_BLK];
    const int b = blockIdx.x, t = threadIdx.x;
    const int i = b * SCAN_BLK + t;
    int v = (i < NN) ? g_cnt[i] : 0;
    sh[t] = v;
    __syncthreads();
    for (int d = 1; d < SCAN_BLK; d <<= 1) {
        int x = (t >= d) ? sh[t - d] : 0;
        __syncthreads();
        sh[t] += x;
        __syncthreads();
    }
    if (i < NN) g_rptr[i] = sh[t] - v;     // exclusive within block
    if (t == SCAN_BLK - 1) g_blksum[b] = sh[t];
}

__global__ void scan_totals_kernel(int nnz) {
    __shared__ int sh[NBLK];
    const int t = threadIdx.x;
    int v = 0;
    if (t < NBLK) { v = g_blksum[t]; sh[t] = v; }
    __syncthreads();
    for (int d = 1; d < NBLK; d <<= 1) {
        int x = (t >= d && t < NBLK) ? sh[t - d] : 0;
        __syncthreads();
        if (t < NBLK) sh[t] += x;
        __syncthreads();
    }
    if (t < NBLK) g_blkoff[t] = sh[t] - v;  // exclusive
    if (t == 0) g_rptr[NN] = nnz;
}

__global__ void scan_fixup_kernel() {
    const int i = blockIdx.x * blockDim.x + threadIdx.x;
    if (i < NN) {
        int r = g_rptr[i] + g_blkoff[blockIdx.x];
        g_rptr[i]   = r;
        g_cursor[i] = r;
    }
}

__global__ void scatter_kernel(const int* __restrict__ rows,
                               const int* __restrict__ cols,
                               const float* __restrict__ vals, int nnz) {
    int i = blockIdx.x * blockDim.x + threadIdx.x;
    if (i < nnz) {
        int r = rows[i];
        int p = atomicAdd(&g_cursor[r], 1);
        g_edges[p] = make_int2(cols[i], __float_as_int(vals[i]));
    }
}

// ---------------- fp32 -> fp16 convert (X -> slot 0) ----------------
__global__ void convert_kernel(const float* __restrict__ X, __half* __restrict__ H) {
    int i = blockIdx.x * blockDim.x + threadIdx.x;          // 4 elems per thread
    if (i < NV2) {
        float4 v = __ldg(&((const float4*)X)[i]);
        __half2 lo = __floats2half2_rn(v.x, v.y);
        __half2 hi = __floats2half2_rn(v.z, v.w);
        uint2 r;
        r.x = *(unsigned int*)&lo;
        r.y = *(unsigned int*)&hi;
        ((uint2*)H)[i] = r;
    }
}

// ---------------- helpers ----------------
__device__ __forceinline__ void fma_h(float4& a, uint2 r, float v) {
    float2 lo = __half22float2(*(const __half2*)&r.x);
    float2 hi = __half22float2(*(const __half2*)&r.y);
    a.x += v * lo.x; a.y += v * lo.y; a.z += v * hi.x; a.w += v * hi.y;
}

__device__ __forceinline__ uint2 pack_h(float4 t) {
    __half2 lo = __floats2half2_rn(t.x, t.y);
    __half2 hi = __floats2half2_rn(t.z, t.w);
    uint2 r;
    r.x = *(unsigned int*)&lo;
    r.y = *(unsigned int*)&hi;
    return r;
}

// SpMM for one row: unroll-4 groups with SOFTWARE-PIPELINED edge prefetch.
// Group g's edge loads are issued during group g-1's gathers/FMAs, so in
// steady state gather addresses are ready immediately (edge-load latency
// only exposed once per row). Same FMA order as the proven R6 loop.
__device__ __forceinline__ float4 spmm_row_h(const __half* __restrict__ T,
                                             int s, int e, int lane) {
    float4 a = make_float4(0.f, 0.f, 0.f, 0.f);
    const uint2* Tv = (const uint2*)T;    // 4 halves per uint2; row stride = 32
    const int g = (e - s) >> 2;           // full groups of 4 edges
    int i = s;

    if (g > 0) {
        int2 e0 = __ldg(&g_edges[i]);
        int2 e1 = __ldg(&g_edges[i + 1]);
        int2 e2 = __ldg(&g_edges[i + 2]);
        int2 e3 = __ldg(&g_edges[i + 3]);

        for (int k = 0; k < g - 1; k++, i += 4) {
            // gathers for current group (addresses already resolved)
            uint2 r0 = __ldg(&Tv[e0.x * 32 + lane]);
            uint2 r1 = __ldg(&Tv[e1.x * 32 + lane]);
            uint2 r2 = __ldg(&Tv[e2.x * 32 + lane]);
            uint2 r3 = __ldg(&Tv[e3.x * 32 + lane]);
            // prefetch next group's edges (overlaps with gathers + FMAs)
            int2 f0 = __ldg(&g_edges[i + 4]);
            int2 f1 = __ldg(&g_edges[i + 5]);
            int2 f2 = __ldg(&g_edges[i + 6]);
            int2 f3 = __ldg(&g_edges[i + 7]);
            fma_h(a, r0, __int_as_float(e0.y));
            fma_h(a, r1, __int_as_float(e1.y));
            fma_h(a, r2, __int_as_float(e2.y));
            fma_h(a, r3, __int_as_float(e3.y));
            e0 = f0; e1 = f1; e2 = f2; e3 = f3;
        }
        // final full group (no prefetch)
        uint2 r0 = __ldg(&Tv[e0.x * 32 + lane]);
        uint2 r1 = __ldg(&Tv[e1.x * 32 + lane]);
        uint2 r2 = __ldg(&Tv[e2.x * 32 + lane]);
        uint2 r3 = __ldg(&Tv[e3.x * 32 + lane]);
        fma_h(a, r0, __int_as_float(e0.y));
        fma_h(a, r1, __int_as_float(e1.y));
        fma_h(a, r2, __int_as_float(e2.y));
        fma_h(a, r3, __int_as_float(e3.y));
        i += 4;
    }
    // remainder (<4 edges)
    for (; i < e; i++) {
        int2 e0 = __ldg(&g_edges[i]);
        uint2 r0 = __ldg(&Tv[e0.x * 32 + lane]);
        fma_h(a, r0, __int_as_float(e0.y));
    }
    return a;
}

// T1 = L @ T0 (slot0 -> slot1); one row per warp
__global__ void cheb_first(const __half* __restrict__ T0,
                           __half* __restrict__ T1) {
    int gw   = (blockIdx.x * blockDim.x + threadIdx.x) >> 5;
    int lane = threadIdx.x & 31;
    if (gw >= NN) return;
    int s = g_rptr[gw], e = g_rptr[gw + 1];

    float4 a = spmm_row_h(T0, s, e, lane);
    ((uint2*)T1)[gw * 32 + lane] = pack_h(a);
}

// Tk = 2*(L @ Tc) - Tp  (slot k-1, slot k-2 -> slot k); one row per warp
__global__ void cheb_step(const __half* __restrict__ Tc,
                          const __half* __restrict__ Tp,
                          __half* __restrict__ Tn) {
    int gw   = (blockIdx.x * blockDim.x + threadIdx.x) >> 5;
    int lane = threadIdx.x & 31;
    if (gw >= NN) return;
    int s = g_rptr[gw], e = g_rptr[gw + 1];

    float4 a = spmm_row_h(Tc, s, e, lane);

    int idx = gw * 32 + lane;
    uint2 tpr = __ldg(&((const uint2*)Tp)[idx]);
    float2 tplo = __half22float2(*(const __half2*)&tpr.x);
    float2 tphi = __half22float2(*(const __half2*)&tpr.y);

    float4 tk;
    tk.x = 2.f * a.x - tplo.x;
    tk.y = 2.f * a.y - tplo.y;
    tk.z = 2.f * a.z - tphi.x;
    tk.w = 2.f * a.w - tphi.y;
    ((uint2*)Tn)[idx] = pack_h(tk);
}

// out = sum_k coeffs[k] * T_k ; descending k so the newest (L2-hot) slots
// are read before eviction.
__global__ void reduce_kernel(const __half* __restrict__ T,
                              const float* __restrict__ coeffs,
                              float* __restrict__ out, int M) {
    int i = blockIdx.x * blockDim.x + threadIdx.x;
    if (i >= NV2) return;
    const uint2* base = (const uint2*)T;
    float4 a = make_float4(0.f, 0.f, 0.f, 0.f);
    int k = M - 1;
    for (; k >= 3; k -= 4) {
        uint2 r0 = __ldg(&base[(size_t)(k - 0) * NV2 + i]);
        uint2 r1 = __ldg(&base[(size_t)(k - 1) * NV2 + i]);
        uint2 r2 = __ldg(&base[(size_t)(k - 2) * NV2 + i]);
        uint2 r3 = __ldg(&base[(size_t)(k - 3) * NV2 + i]);
        fma_h(a, r0, __ldg(&coeffs[k - 0]));
        fma_h(a, r1, __ldg(&coeffs[k - 1]));
        fma_h(a, r2, __ldg(&coeffs[k - 2]));
        fma_h(a, r3, __ldg(&coeffs[k - 3]));
    }
    for (; k >= 0; k--) {
        uint2 r = __ldg(&base[(size_t)k * NV2 + i]);
        fma_h(a, r, __ldg(&coeffs[k]));
    }
    ((float4*)out)[i] = a;
}

// ---------------- launch ----------------
extern "C" void kernel_launch(void* const* d_in, const int* in_sizes, int n_in,
                              void* d_out, int out_size) {
    const int*   rows   = (const int*)d_in[0];
    const int*   cols   = (const int*)d_in[1];
    const float* vals   = (const float*)d_in[2];
    const float* X      = (const float*)d_in[3];
    const float* coeffs = (const float*)d_in[4];
    const int nnz = in_sizes[0];
    const int M   = in_sizes[4];

    void* p;
    __half* T;
    int* pcnt;
    cudaGetSymbolAddress(&p, g_T);   T = (__half*)p;
    cudaGetSymbolAddress(&p, g_cnt); pcnt = (int*)p;

    const size_t SLOT = (size_t)NN * DD;

    // ---- CSR build (in-graph, re-done every replay) ----
    cudaMemsetAsync(pcnt, 0, NN * sizeof(int));
    hist_kernel<<<(nnz + 255) / 256, 256>>>(rows, nnz);
    scan_blocks_kernel<<<NBLK, SCAN_BLK>>>();
    scan_totals_kernel<<<1, SCAN_BLK>>>(nnz);
    scan_fixup_kernel<<<NBLK, SCAN_BLK>>>();
    scatter_kernel<<<(nnz + 255) / 256, 256>>>(rows, cols, vals, nnz);

    // ---- X -> fp16 slot 0 ----
    convert_kernel<<<(NV2 + 255) / 256, 256>>>(X, T);

    // ---- Chebyshev recurrence: slot k = T_k (one row per warp) ----
    const int threads = 256;                 // 8 rows per block
    const int rowsPerBlk = threads / 32;
    const int grid = (NN + rowsPerBlk - 1) / rowsPerBlk;

    cheb_first<<<grid, threads>>>(T, T + SLOT);
    for (int k = 2; k < M; k++) {
        cheb_step<<<grid, threads>>>(T + (size_t)(k - 1) * SLOT,
                                     T + (size_t)(k - 2) * SLOT,
                                     T + (size_t)k * SLOT);
    }

    // ---- final weighted reduction (descending k) ----
    reduce_kernel<<<(NV2 + 255) / 256, 256>>>(T, coeffs, (float*)d_out, M);
}

// round 13
// speedup vs baseline: 1.0984x; 1.0984x over previous
#include <cuda_runtime.h>
#include <cuda_fp16.h>

#define NN   50000
#define DD   128
#define NV2  (NN * DD / 4)      // uint2 (4 halves) per T slot = 1.6M
#define NNZ_CAP 800000
#define MCAP 32

#define SCAN_BLK 256
#define NBLK ((NN + SCAN_BLK - 1) / SCAN_BLK)   // 196

// ---- static scratch (allocation-free rule: __device__ globals) ----
__device__ __half g_T[MCAP * NN * DD];   // all Chebyshev iterates, fp16 (slot k = T_k)
__device__ float g_acc[NN * DD];         // fp32 partial accumulator
__device__ int   g_cnt[NN];
__device__ int   g_rptr[NN + 1];
__device__ int   g_cursor[NN];
__device__ int   g_blksum[NBLK];
__device__ int   g_blkoff[NBLK];
__device__ int2  g_edges[NNZ_CAP];       // {col, val-as-int}

// ---------------- CSR build (R10-proven 3-kernel scan) ----------------
__global__ void hist_kernel(const int* __restrict__ rows, int nnz) {
    int i = blockIdx.x * blockDim.x + threadIdx.x;
    if (i < nnz) atomicAdd(&g_cnt[rows[i]], 1);
}

__global__ void scan_blocks_kernel() {
    __shared__ int sh[SCAN_BLK];
    const int b = blockIdx.x, t = threadIdx.x;
    const int i = b * SCAN_BLK + t;
    int v = (i < NN) ? g_cnt[i] : 0;
    sh[t] = v;
    __syncthreads();
    for (int d = 1; d < SCAN_BLK; d <<= 1) {
        int x = (t >= d) ? sh[t - d] : 0;
        __syncthreads();
        sh[t] += x;
        __syncthreads();
    }
    if (i < NN) g_rptr[i] = sh[t] - v;     // exclusive within block
    if (t == SCAN_BLK - 1) g_blksum[b] = sh[t];
}

__global__ void scan_totals_kernel(int nnz) {
    __shared__ int sh[NBLK];
    const int t = threadIdx.x;
    int v = 0;
    if (t < NBLK) { v = g_blksum[t]; sh[t] = v; }
    __syncthreads();
    for (int d = 1; d < NBLK; d <<= 1) {
        int x = (t >= d && t < NBLK) ? sh[t - d] : 0;
        __syncthreads();
        if (t < NBLK) sh[t] += x;
        __syncthreads();
    }
    if (t < NBLK) g_blkoff[t] = sh[t] - v;  // exclusive
    if (t == 0) g_rptr[NN] = nnz;
}

__global__ void scan_fixup_kernel() {
    const int i = blockIdx.x * blockDim.x + threadIdx.x;
    if (i < NN) {
        int r = g_rptr[i] + g_blkoff[blockIdx.x];
        g_rptr[i]   = r;
        g_cursor[i] = r;
    }
}

__global__ void scatter_kernel(const int* __restrict__ rows,
                               const int* __restrict__ cols,
                               const float* __restrict__ vals, int nnz) {
    int i = blockIdx.x * blockDim.x + threadIdx.x;
    if (i < nnz) {
        int r = rows[i];
        int p = atomicAdd(&g_cursor[r], 1);
        g_edges[p] = make_int2(cols[i], __float_as_int(vals[i]));
    }
}

// ---------------- fp32 -> fp16 convert (X -> slot 0) ----------------
__global__ void convert_kernel(const float* __restrict__ X, __half* __restrict__ H) {
    int i = blockIdx.x * blockDim.x + threadIdx.x;          // 4 elems per thread
    if (i < NV2) {
        float4 v = __ldg(&((const float4*)X)[i]);
        __half2 lo = __floats2half2_rn(v.x, v.y);
        __half2 hi = __floats2half2_rn(v.z, v.w);
        uint2 r;
        r.x = *(unsigned int*)&lo;
        r.y = *(unsigned int*)&hi;
        ((uint2*)H)[i] = r;
    }
}

// ---------------- helpers ----------------
__device__ __forceinline__ void fma_h(float4& a, uint2 r, float v) {
    float2 lo = __half22float2(*(const __half2*)&r.x);
    float2 hi = __half22float2(*(const __half2*)&r.y);
    a.x += v * lo.x; a.y += v * lo.y; a.z += v * hi.x; a.w += v * hi.y;
}

__device__ __forceinline__ uint2 pack_h(float4 t) {
    __half2 lo = __floats2half2_rn(t.x, t.y);
    __half2 hi = __floats2half2_rn(t.z, t.w);
    uint2 r;
    r.x = *(unsigned int*)&lo;
    r.y = *(unsigned int*)&hi;
    return r;
}

// SpMM for one row (R6/R10-proven form: unroll-by-4, broadcast edge loads).
// DO NOT TOUCH — four restructurings of this loop all regressed.
__device__ __forceinline__ float4 spmm_row_h(const __half* __restrict__ T,
                                             int s, int e, int lane) {
    float4 a = make_float4(0.f, 0.f, 0.f, 0.f);
    const uint2* Tv = (const uint2*)T;    // 4 halves per uint2; row stride = 32
    int i = s;
    for (; i + 3 < e; i += 4) {
        int2 e0 = __ldg(&g_edges[i]);
        int2 e1 = __ldg(&g_edges[i + 1]);
        int2 e2 = __ldg(&g_edges[i + 2]);
        int2 e3 = __ldg(&g_edges[i + 3]);
        uint2 r0 = __ldg(&Tv[e0.x * 32 + lane]);
        uint2 r1 = __ldg(&Tv[e1.x * 32 + lane]);
        uint2 r2 = __ldg(&Tv[e2.x * 32 + lane]);
        uint2 r3 = __ldg(&Tv[e3.x * 32 + lane]);
        fma_h(a, r0, __int_as_float(e0.y));
        fma_h(a, r1, __int_as_float(e1.y));
        fma_h(a, r2, __int_as_float(e2.y));
        fma_h(a, r3, __int_as_float(e3.y));
    }
    for (; i < e; i++) {
        int2 e0 = __ldg(&g_edges[i]);
        uint2 r0 = __ldg(&Tv[e0.x * 32 + lane]);
        fma_h(a, r0, __int_as_float(e0.y));
    }
    return a;
}

// T1 = L @ T0 (slot0 -> slot1); one row per warp
__global__ void cheb_first(const __half* __restrict__ T0,
                           __half* __restrict__ T1) {
    int gw   = (blockIdx.x * blockDim.x + threadIdx.x) >> 5;
    int lane = threadIdx.x & 31;
    if (gw >= NN) return;
    int s = g_rptr[gw], e = g_rptr[gw + 1];

    float4 a = spmm_row_h(T0, s, e, lane);
    ((uint2*)T1)[gw * 32 + lane] = pack_h(a);
}

// Tk = 2*(L @ Tc) - Tp  (plain; byte-identical behavior to R10)
__global__ void cheb_step(const __half* __restrict__ Tc,
                          const __half* __restrict__ Tp,
                          __half* __restrict__ Tn) {
    int gw   = (blockIdx.x * blockDim.x + threadIdx.x) >> 5;
    int lane = threadIdx.x & 31;
    if (gw >= NN) return;
    int s = g_rptr[gw], e = g_rptr[gw + 1];

    float4 a = spmm_row_h(Tc, s, e, lane);

    int idx = gw * 32 + lane;
    uint2 tpr = __ldg(&((const uint2*)Tp)[idx]);
    float2 tplo = __half22float2(*(const __half2*)&tpr.x);
    float2 tphi = __half22float2(*(const __half2*)&tpr.y);

    float4 tk;
    tk.x = 2.f * a.x - tplo.x;
    tk.y = 2.f * a.y - tplo.y;
    tk.z = 2.f * a.z - tphi.x;
    tk.w = 2.f * a.w - tphi.y;
    ((uint2*)Tn)[idx] = pack_h(tk);
}

// Same step + fused partial reduction of finalized slots [r0, r1) into g_acc.
// The streaming slot reads ride the idle DRAM pipe / spare issue slots of the
// latency-bound SpMM.
__global__ void cheb_step_fused(const __half* __restrict__ Tc,
                                const __half* __restrict__ Tp,
                                __half* __restrict__ Tn,
                                const __half* __restrict__ slab,
                                const float* __restrict__ coeffs,
                                float* __restrict__ acc,
                                int r0, int r1, int writeMode) {
    int gw   = (blockIdx.x * blockDim.x + threadIdx.x) >> 5;
    int lane = threadIdx.x & 31;
    if (gw >= NN) return;
    int s = g_rptr[gw], e = g_rptr[gw + 1];

    float4 a = spmm_row_h(Tc, s, e, lane);

    int idx = gw * 32 + lane;
    uint2 tpr = __ldg(&((const uint2*)Tp)[idx]);
    float2 tplo = __half22float2(*(const __half2*)&tpr.x);
    float2 tphi = __half22float2(*(const __half2*)&tpr.y);

    float4 tk;
    tk.x = 2.f * a.x - tplo.x;
    tk.y = 2.f * a.y - tplo.y;
    tk.z = 2.f * a.z - tphi.x;
    tk.w = 2.f * a.w - tphi.y;
    ((uint2*)Tn)[idx] = pack_h(tk);

    // ---- fused partial reduction over slots [r0, r1) ----
    const uint2* sl = (const uint2*)slab;
    float4 p = make_float4(0.f, 0.f, 0.f, 0.f);
    if (!writeMode) p = ((const float4*)acc)[idx];
    int j = r0;
    for (; j + 1 < r1; j += 2) {
        uint2 q0 = __ldg(&sl[(size_t)(j + 0) * NV2 + idx]);
        uint2 q1 = __ldg(&sl[(size_t)(j + 1) * NV2 + idx]);
        fma_h(p, q0, __ldg(&coeffs[j + 0]));
        fma_h(p, q1, __ldg(&coeffs[j + 1]));
    }
    if (j < r1) {
        uint2 q0 = __ldg(&sl[(size_t)j * NV2 + idx]);
        fma_h(p, q0, __ldg(&coeffs[j]));
    }
    ((float4*)acc)[idx] = p;
}

// out = g_acc + sum_{k=r0}^{M-1} c_k T_k  (descending k: newest slots L2-hot)
__global__ void final_reduce_kernel(const __half* __restrict__ T,
                                    const float* __restrict__ coeffs,
                                    const float* __restrict__ acc,
                                    float* __restrict__ out, int r0, int M) {
    int i = blockIdx.x * blockDim.x + threadIdx.x;
    if (i >= NV2) return;
    const uint2* base = (const uint2*)T;
    float4 a = ((const float4*)acc)[i];
    int k = M - 1;
    for (; k >= r0 + 3; k -= 4) {
        uint2 r0v = __ldg(&base[(size_t)(k - 0) * NV2 + i]);
        uint2 r1v = __ldg(&base[(size_t)(k - 1) * NV2 + i]);
        uint2 r2v = __ldg(&base[(size_t)(k - 2) * NV2 + i]);
        uint2 r3v = __ldg(&base[(size_t)(k - 3) * NV2 + i]);
        fma_h(a, r0v, __ldg(&coeffs[k - 0]));
        fma_h(a, r1v, __ldg(&coeffs[k - 1]));
        fma_h(a, r2v, __ldg(&coeffs[k - 2]));
        fma_h(a, r3v, __ldg(&coeffs[k - 3]));
    }
    for (; k >= r0; k--) {
        uint2 r = __ldg(&base[(size_t)k * NV2 + i]);
        fma_h(a, r, __ldg(&coeffs[k]));
    }
    ((float4*)out)[i] = a;
}

// Fallback full reduce (R10 form) for small M
__global__ void reduce_kernel(const __half* __restrict__ T,
                              const float* __restrict__ coeffs,
                              float* __restrict__ out, int M) {
    int i = blockIdx.x * blockDim.x + threadIdx.x;
    if (i >= NV2) return;
    const uint2* base = (const uint2*)T;
    float4 a = make_float4(0.f, 0.f, 0.f, 0.f);
    int k = M - 1;
    for (; k >= 3; k -= 4) {
        uint2 r0 = __ldg(&base[(size_t)(k - 0) * NV2 + i]);
        uint2 r1 = __ldg(&base[(size_t)(k - 1) * NV2 + i]);
        uint2 r2 = __ldg(&base[(size_t)(k - 2) * NV2 + i]);
        uint2 r3 = __ldg(&base[(size_t)(k - 3) * NV2 + i]);
        fma_h(a, r0, __ldg(&coeffs[k - 0]));
        fma_h(a, r1, __ldg(&coeffs[k - 1]));
        fma_h(a, r2, __ldg(&coeffs[k - 2]));
        fma_h(a, r3, __ldg(&coeffs[k - 3]));
    }
    for (; k >= 0; k--) {
        uint2 r = __ldg(&base[(size_t)k * NV2 + i]);
        fma_h(a, r, __ldg(&coeffs[k]));
    }
    ((float4*)out)[i] = a;
}

// ---------------- launch ----------------
extern "C" void kernel_launch(void* const* d_in, const int* in_sizes, int n_in,
                              void* d_out, int out_size) {
    const int*   rows   = (const int*)d_in[0];
    const int*   cols   = (const int*)d_in[1];
    const float* vals   = (const float*)d_in[2];
    const float* X      = (const float*)d_in[3];
    const float* coeffs = (const float*)d_in[4];
    const int nnz = in_sizes[0];
    const int M   = in_sizes[4];

    void* p;
    __half* T;
    float* acc;
    int* pcnt;
    cudaGetSymbolAddress(&p, g_T);   T = (__half*)p;
    cudaGetSymbolAddress(&p, g_acc); acc = (float*)p;
    cudaGetSymbolAddress(&p, g_cnt); pcnt = (int*)p;

    const size_t SLOT = (size_t)NN * DD;

    // ---- CSR build (in-graph, re-done every replay) ----
    cudaMemsetAsync(pcnt, 0, NN * sizeof(int));
    hist_kernel<<<(nnz + 255) / 256, 256>>>(rows, nnz);
    scan_blocks_kernel<<<NBLK, SCAN_BLK>>>();
    scan_totals_kernel<<<1, SCAN_BLK>>>(nnz);
    scan_fixup_kernel<<<NBLK, SCAN_BLK>>>();
    scatter_kernel<<<(nnz + 255) / 256, 256>>>(rows, cols, vals, nnz);

    // ---- X -> fp16 slot 0 ----
    convert_kernel<<<(NV2 + 255) / 256, 256>>>(X, T);

    // ---- Chebyshev recurrence: slot k = T_k (one row per warp) ----
    const int threads = 256;                 // 8 rows per block
    const int rowsPerBlk = threads / 32;
    const int grid = (NN + rowsPerBlk - 1) / rowsPerBlk;

    cheb_first<<<grid, threads>>>(T, T + SLOT);

    if (M >= 24) {
        for (int k = 2; k < M; k++) {
            const __half* Tc = T + (size_t)(k - 1) * SLOT;
            const __half* Tp = T + (size_t)(k - 2) * SLOT;
            __half*       Tn = T + (size_t)k * SLOT;
            if (k == 11) {
                cheb_step_fused<<<grid, threads>>>(Tc, Tp, Tn, T, coeffs, acc,
                                                   0, 10, 1);
            } else if (k == 21) {
                cheb_step_fused<<<grid, threads>>>(Tc, Tp, Tn, T, coeffs, acc,
                                                   10, 20, 0);
            } else {
                cheb_step<<<grid, threads>>>(Tc, Tp, Tn);
            }
        }
        final_reduce_kernel<<<(NV2 + 255) / 256, 256>>>(T, coeffs, acc,
                                                        (float*)d_out, 20, M);
    } else {
        for (int k = 2; k < M; k++) {
            cheb_step<<<grid, threads>>>(T + (size_t)(k - 1) * SLOT,
                                         T + (size_t)(k - 2) * SLOT,
                                         T + (size_t)k * SLOT);
        }
        reduce_kernel<<<(NV2 + 255) / 256, 256>>>(T, coeffs, (float*)d_out, M);
    }
}

// round 14
// speedup vs baseline: 1.1807x; 1.0749x over previous
#include <cuda_runtime.h>
#include <cuda_fp16.h>

#define NN   50000
#define DD   128
#define NV2  (NN * DD / 4)      // uint2 (4 halves) per T buffer = 1.6M
#define NNZ_CAP 800000

#define SCAN_BLK 256
#define NBLK ((NN + SCAN_BLK - 1) / SCAN_BLK)   // 196

// ---- static scratch (allocation-free rule: __device__ globals) ----
__device__ __half g_b0[NN * DD];     // rotating Chebyshev buffers (fp16)
__device__ __half g_b1[NN * DD];
__device__ __half g_b2[NN * DD];
__device__ int   g_cnt[NN];
__device__ int   g_rptr[NN + 1];
__device__ int   g_cursor[NN];
__device__ int   g_blksum[NBLK];
__device__ int   g_blkoff[NBLK];
__device__ int2  g_edges[NNZ_CAP];   // {col, val-as-int}

// ---------------- CSR build (R10-proven 3-kernel scan) ----------------
__global__ void hist_kernel(const int* __restrict__ rows, int nnz) {
    int i = blockIdx.x * blockDim.x + threadIdx.x;
    if (i < nnz) atomicAdd(&g_cnt[rows[i]], 1);
}

__global__ void scan_blocks_kernel() {
    __shared__ int sh[SCAN_BLK];
    const int b = blockIdx.x, t = threadIdx.x;
    const int i = b * SCAN_BLK + t;
    int v = (i < NN) ? g_cnt[i] : 0;
    sh[t] = v;
    __syncthreads();
    for (int d = 1; d < SCAN_BLK; d <<= 1) {
        int x = (t >= d) ? sh[t - d] : 0;
        __syncthreads();
        sh[t] += x;
        __syncthreads();
    }
    if (i < NN) g_rptr[i] = sh[t] - v;     // exclusive within block
    if (t == SCAN_BLK - 1) g_blksum[b] = sh[t];
}

__global__ void scan_totals_kernel(int nnz) {
    __shared__ int sh[NBLK];
    const int t = threadIdx.x;
    int v = 0;
    if (t < NBLK) { v = g_blksum[t]; sh[t] = v; }
    __syncthreads();
    for (int d = 1; d < NBLK; d <<= 1) {
        int x = (t >= d && t < NBLK) ? sh[t - d] : 0;
        __syncthreads();
        if (t < NBLK) sh[t] += x;
        __syncthreads();
    }
    if (t < NBLK) g_blkoff[t] = sh[t] - v;  // exclusive
    if (t == 0) g_rptr[NN] = nnz;
}

__global__ void scan_fixup_kernel() {
    const int i = blockIdx.x * blockDim.x + threadIdx.x;
    if (i < NN) {
        int r = g_rptr[i] + g_blkoff[blockIdx.x];
        g_rptr[i]   = r;
        g_cursor[i] = r;
    }
}

__global__ void scatter_kernel(const int* __restrict__ rows,
                               const int* __restrict__ cols,
                               const float* __restrict__ vals, int nnz) {
    int i = blockIdx.x * blockDim.x + threadIdx.x;
    if (i < nnz) {
        int r = rows[i];
        int p = atomicAdd(&g_cursor[r], 1);
        g_edges[p] = make_int2(cols[i], __float_as_int(vals[i]));
    }
}

// ---------------- fp32 -> fp16 convert (X -> buffer 0) ----------------
__global__ void convert_kernel(const float* __restrict__ X, __half* __restrict__ H) {
    int i = blockIdx.x * blockDim.x + threadIdx.x;          // 4 elems per thread
    if (i < NV2) {
        float4 v = __ldg(&((const float4*)X)[i]);
        __half2 lo = __floats2half2_rn(v.x, v.y);
        __half2 hi = __floats2half2_rn(v.z, v.w);
        uint2 r;
        r.x = *(unsigned int*)&lo;
        r.y = *(unsigned int*)&hi;
        ((uint2*)H)[i] = r;
    }
}

// ---------------- helpers ----------------
__device__ __forceinline__ void fma_h(float4& a, uint2 r, float v) {
    float2 lo = __half22float2(*(const __half2*)&r.x);
    float2 hi = __half22float2(*(const __half2*)&r.y);
    a.x += v * lo.x; a.y += v * lo.y; a.z += v * hi.x; a.w += v * hi.y;
}

__device__ __forceinline__ uint2 pack_h(float4 t) {
    __half2 lo = __floats2half2_rn(t.x, t.y);
    __half2 hi = __floats2half2_rn(t.z, t.w);
    uint2 r;
    r.x = *(unsigned int*)&lo;
    r.y = *(unsigned int*)&hi;
    return r;
}

// SpMM for one row (R6/R10-proven form: unroll-by-4, broadcast edge loads).
// DO NOT TOUCH — five restructurings of this loop all regressed.
__device__ __forceinline__ float4 spmm_row_h(const __half* __restrict__ T,
                                             int s, int e, int lane) {
    float4 a = make_float4(0.f, 0.f, 0.f, 0.f);
    const uint2* Tv = (const uint2*)T;    // 4 halves per uint2; row stride = 32
    int i = s;
    for (; i + 3 < e; i += 4) {
        int2 e0 = __ldg(&g_edges[i]);
        int2 e1 = __ldg(&g_edges[i + 1]);
        int2 e2 = __ldg(&g_edges[i + 2]);
        int2 e3 = __ldg(&g_edges[i + 3]);
        uint2 r0 = __ldg(&Tv[e0.x * 32 + lane]);
        uint2 r1 = __ldg(&Tv[e1.x * 32 + lane]);
        uint2 r2 = __ldg(&Tv[e2.x * 32 + lane]);
        uint2 r3 = __ldg(&Tv[e3.x * 32 + lane]);
        fma_h(a, r0, __int_as_float(e0.y));
        fma_h(a, r1, __int_as_float(e1.y));
        fma_h(a, r2, __int_as_float(e2.y));
        fma_h(a, r3, __int_as_float(e3.y));
    }
    for (; i < e; i++) {
        int2 e0 = __ldg(&g_edges[i]);
        uint2 r0 = __ldg(&Tv[e0.x * 32 + lane]);
        fma_h(a, r0, __int_as_float(e0.y));
    }
    return a;
}

// T1 = L @ T0 ; out = c0*X + c1*T1
__global__ void cheb_first_acc(const __half* __restrict__ T0h,
                               const float* __restrict__ X,
                               __half* __restrict__ T1,
                               float* __restrict__ out,
                               const float* __restrict__ coeffs) {
    int gw   = (blockIdx.x * blockDim.x + threadIdx.x) >> 5;
    int lane = threadIdx.x & 31;
    if (gw >= NN) return;
    int s = g_rptr[gw], e = g_rptr[gw + 1];

    float4 a = spmm_row_h(T0h, s, e, lane);

    int idx = gw * 32 + lane;
    ((uint2*)T1)[idx] = pack_h(a);

    float4 x0 = __ldg(&((const float4*)X)[idx]);
    float c0 = __ldg(&coeffs[0]), c1 = __ldg(&coeffs[1]);
    float4 o;
    o.x = c0 * x0.x + c1 * a.x;
    o.y = c0 * x0.y + c1 * a.y;
    o.z = c0 * x0.z + c1 * a.z;
    o.w = c0 * x0.w + c1 * a.w;
    ((float4*)out)[idx] = o;
}

// Tk = 2*(L @ Tc) - Tp  (plain; byte-identical behavior to R10)
__global__ void cheb_step(const __half* __restrict__ Tc,
                          const __half* __restrict__ Tp,
                          __half* __restrict__ Tn) {
    int gw   = (blockIdx.x * blockDim.x + threadIdx.x) >> 5;
    int lane = threadIdx.x & 31;
    if (gw >= NN) return;
    int s = g_rptr[gw], e = g_rptr[gw + 1];

    float4 a = spmm_row_h(Tc, s, e, lane);

    int idx = gw * 32 + lane;
    uint2 tpr = __ldg(&((const uint2*)Tp)[idx]);
    float2 tplo = __half22float2(*(const __half2*)&tpr.x);
    float2 tphi = __half22float2(*(const __half2*)&tpr.y);

    float4 tk;
    tk.x = 2.f * a.x - tplo.x;
    tk.y = 2.f * a.y - tplo.y;
    tk.z = 2.f * a.z - tphi.x;
    tk.w = 2.f * a.w - tphi.y;
    ((uint2*)Tn)[idx] = pack_h(tk);
}

// Step + pair accumulation: out += c_{k-1}*Tc + c_k*Tk.
// Tc/out reads are small L2-hot streams riding the latency-bound SpMM.
__global__ void cheb_step_pair(const __half* __restrict__ Tc,
                               const __half* __restrict__ Tp,
                               __half* __restrict__ Tn,
                               float* __restrict__ out,
                               const float* __restrict__ coeffs, int k) {
    int gw   = (blockIdx.x * blockDim.x + threadIdx.x) >> 5;
    int lane = threadIdx.x & 31;
    if (gw >= NN) return;
    int s = g_rptr[gw], e = g_rptr[gw + 1];

    float4 a = spmm_row_h(Tc, s, e, lane);

    int idx = gw * 32 + lane;
    uint2 tpr = __ldg(&((const uint2*)Tp)[idx]);
    float2 tplo = __half22float2(*(const __half2*)&tpr.x);
    float2 tphi = __half22float2(*(const __half2*)&tpr.y);

    float4 tk;
    tk.x = 2.f * a.x - tplo.x;
    tk.y = 2.f * a.y - tplo.y;
    tk.z = 2.f * a.z - tphi.x;
    tk.w = 2.f * a.w - tphi.y;
    ((uint2*)Tn)[idx] = pack_h(tk);

    // pair accumulate (fp32)
    uint2 tcr = __ldg(&((const uint2*)Tc)[idx]);
    float ckm1 = __ldg(&coeffs[k - 1]);
    float ck   = __ldg(&coeffs[k]);
    float4 o = ((const float4*)out)[idx];
    fma_h(o, tcr, ckm1);
    o.x += ck * tk.x;
    o.y += ck * tk.y;
    o.z += ck * tk.z;
    o.w += ck * tk.w;
    ((float4*)out)[idx] = o;
}

// tail fixup for general M: out += c_j * Tj
__global__ void tail_acc_kernel(const __half* __restrict__ Tj,
                                const float* __restrict__ coeffs,
                                float* __restrict__ out, int j) {
    int i = blockIdx.x * blockDim.x + threadIdx.x;
    if (i >= NV2) return;
    uint2 r = __ldg(&((const uint2*)Tj)[i]);
    float4 o = ((const float4*)out)[i];
    fma_h(o, r, __ldg(&coeffs[j]));
    ((float4*)out)[i] = o;
}

// ---------------- launch ----------------
extern "C" void kernel_launch(void* const* d_in, const int* in_sizes, int n_in,
                              void* d_out, int out_size) {
    const int*   rows   = (const int*)d_in[0];
    const int*   cols   = (const int*)d_in[1];
    const float* vals   = (const float*)d_in[2];
    const float* X      = (const float*)d_in[3];
    const float* coeffs = (const float*)d_in[4];
    const int nnz = in_sizes[0];
    const int M   = in_sizes[4];

    void* p;
    __half* buf[3];
    int* pcnt;
    cudaGetSymbolAddress(&p, g_b0);  buf[0] = (__half*)p;
    cudaGetSymbolAddress(&p, g_b1);  buf[1] = (__half*)p;
    cudaGetSymbolAddress(&p, g_b2);  buf[2] = (__half*)p;
    cudaGetSymbolAddress(&p, g_cnt); pcnt = (int*)p;

    float* outp = (float*)d_out;

    // ---- CSR build (in-graph, re-done every replay) ----
    cudaMemsetAsync(pcnt, 0, NN * sizeof(int));
    hist_kernel<<<(nnz + 255) / 256, 256>>>(rows, nnz);
    scan_blocks_kernel<<<NBLK, SCAN_BLK>>>();
    scan_totals_kernel<<<1, SCAN_BLK>>>(nnz);
    scan_fixup_kernel<<<NBLK, SCAN_BLK>>>();
    scatter_kernel<<<(nnz + 255) / 256, 256>>>(rows, cols, vals, nnz);

    // ---- X -> fp16 buffer 0 (T0) ----
    convert_kernel<<<(NV2 + 255) / 256, 256>>>(X, buf[0]);

    // ---- Chebyshev recurrence, rotating buffers, pair accumulation ----
    const int threads = 256;                 // 8 rows per block
    const int rowsPerBlk = threads / 32;
    const int grid = (NN + rowsPerBlk - 1) / rowsPerBlk;

    // T1 = L T0, out = c0*X + c1*T1   (T_k lives in buf[k % 3])
    cheb_first_acc<<<grid, threads>>>(buf[0], X, buf[1], outp, coeffs);

    for (int k = 2; k < M; k++) {
        const __half* Tc = buf[(k - 1) % 3];
        const __half* Tp = buf[(k - 2) % 3];
        __half*       Tn = buf[k % 3];
        if (k & 1) {   // odd k: accumulate c_{k-1} and c_k
            cheb_step_pair<<<grid, threads>>>(Tc, Tp, Tn, outp, coeffs, k);
        } else {
            cheb_step<<<grid, threads>>>(Tc, Tp, Tn);
        }
    }

    // tail: if last computed index M-1 is even, c_{M-1} was not accumulated
    if (M > 2 && ((M - 1) & 1) == 0) {
        tail_acc_kernel<<<(NV2 + 255) / 256, 256>>>(buf[(M - 1) % 3], coeffs,
                                                    outp, M - 1);
    }
}

// round 15
// speedup vs baseline: 1.1948x; 1.0119x over previous
#include <cuda_runtime.h>
#include <cuda_fp16.h>

#define NN   50000
#define DD   128
#define NV2  (NN * DD / 4)      // uint2 (4 halves) per T buffer = 1.6M
#define NNZ_CAP 800000

#define SCAN_BLK 256
#define NBLK ((NN + SCAN_BLK - 1) / SCAN_BLK)   // 196

// ---- static scratch (allocation-free rule: __device__ globals) ----
__device__ __half g_b0[NN * DD];     // rotating Chebyshev buffers (fp16): T_k -> buf[k%4]
__device__ __half g_b1[NN * DD];
__device__ __half g_b2[NN * DD];
__device__ __half g_b3[NN * DD];
__device__ int   g_cnt[NN];
__device__ int   g_rptr[NN + 1];
__device__ int   g_cursor[NN];
__device__ int   g_blksum[NBLK];
__device__ int   g_blkoff[NBLK];
__device__ int2  g_edges[NNZ_CAP];   // {col, val-as-int}

// ---------------- CSR build (R10-proven 3-kernel scan) ----------------
__global__ void hist_kernel(const int* __restrict__ rows, int nnz) {
    int i = blockIdx.x * blockDim.x + threadIdx.x;
    if (i < nnz) atomicAdd(&g_cnt[rows[i]], 1);
}

__global__ void scan_blocks_kernel() {
    __shared__ int sh[SCAN_BLK];
    const int b = blockIdx.x, t = threadIdx.x;
    const int i = b * SCAN_BLK + t;
    int v = (i < NN) ? g_cnt[i] : 0;
    sh[t] = v;
    __syncthreads();
    for (int d = 1; d < SCAN_BLK; d <<= 1) {
        int x = (t >= d) ? sh[t - d] : 0;
        __syncthreads();
        sh[t] += x;
        __syncthreads();
    }
    if (i < NN) g_rptr[i] = sh[t] - v;     // exclusive within block
    if (t == SCAN_BLK - 1) g_blksum[b] = sh[t];
}

__global__ void scan_totals_kernel(int nnz) {
    __shared__ int sh[NBLK];
    const int t = threadIdx.x;
    int v = 0;
    if (t < NBLK) { v = g_blksum[t]; sh[t] = v; }
    __syncthreads();
    for (int d = 1; d < NBLK; d <<= 1) {
        int x = (t >= d && t < NBLK) ? sh[t - d] : 0;
        __syncthreads();
        if (t < NBLK) sh[t] += x;
        __syncthreads();
    }
    if (t < NBLK) g_blkoff[t] = sh[t] - v;  // exclusive
    if (t == 0) g_rptr[NN] = nnz;
}

__global__ void scan_fixup_kernel() {
    const int i = blockIdx.x * blockDim.x + threadIdx.x;
    if (i < NN) {
        int r = g_rptr[i] + g_blkoff[blockIdx.x];
        g_rptr[i]   = r;
        g_cursor[i] = r;
    }
}

__global__ void scatter_kernel(const int* __restrict__ rows,
                               const int* __restrict__ cols,
                               const float* __restrict__ vals, int nnz) {
    int i = blockIdx.x * blockDim.x + threadIdx.x;
    if (i < nnz) {
        int r = rows[i];
        int p = atomicAdd(&g_cursor[r], 1);
        g_edges[p] = make_int2(cols[i], __float_as_int(vals[i]));
    }
}

// ---------------- fp32 -> fp16 convert (X -> buffer 0) ----------------
__global__ void convert_kernel(const float* __restrict__ X, __half* __restrict__ H) {
    int i = blockIdx.x * blockDim.x + threadIdx.x;          // 4 elems per thread
    if (i < NV2) {
        float4 v = __ldg(&((const float4*)X)[i]);
        __half2 lo = __floats2half2_rn(v.x, v.y);
        __half2 hi = __floats2half2_rn(v.z, v.w);
        uint2 r;
        r.x = *(unsigned int*)&lo;
        r.y = *(unsigned int*)&hi;
        ((uint2*)H)[i] = r;
    }
}

// ---------------- helpers ----------------
__device__ __forceinline__ void fma_h(float4& a, uint2 r, float v) {
    float2 lo = __half22float2(*(const __half2*)&r.x);
    float2 hi = __half22float2(*(const __half2*)&r.y);
    a.x += v * lo.x; a.y += v * lo.y; a.z += v * hi.x; a.w += v * hi.y;
}

__device__ __forceinline__ uint2 pack_h(float4 t) {
    __half2 lo = __floats2half2_rn(t.x, t.y);
    __half2 hi = __floats2half2_rn(t.z, t.w);
    uint2 r;
    r.x = *(unsigned int*)&lo;
    r.y = *(unsigned int*)&hi;
    return r;
}

// SpMM for one row (R6/R10-proven form: unroll-by-4, broadcast edge loads).
// DO NOT TOUCH — five restructurings of this loop all regressed.
__device__ __forceinline__ float4 spmm_row_h(const __half* __restrict__ T,
                                             int s, int e, int lane) {
    float4 a = make_float4(0.f, 0.f, 0.f, 0.f);
    const uint2* Tv = (const uint2*)T;    // 4 halves per uint2; row stride = 32
    int i = s;
    for (; i + 3 < e; i += 4) {
        int2 e0 = __ldg(&g_edges[i]);
        int2 e1 = __ldg(&g_edges[i + 1]);
        int2 e2 = __ldg(&g_edges[i + 2]);
        int2 e3 = __ldg(&g_edges[i + 3]);
        uint2 r0 = __ldg(&Tv[e0.x * 32 + lane]);
        uint2 r1 = __ldg(&Tv[e1.x * 32 + lane]);
        uint2 r2 = __ldg(&Tv[e2.x * 32 + lane]);
        uint2 r3 = __ldg(&Tv[e3.x * 32 + lane]);
        fma_h(a, r0, __int_as_float(e0.y));
        fma_h(a, r1, __int_as_float(e1.y));
        fma_h(a, r2, __int_as_float(e2.y));
        fma_h(a, r3, __int_as_float(e3.y));
    }
    for (; i < e; i++) {
        int2 e0 = __ldg(&g_edges[i]);
        uint2 r0 = __ldg(&Tv[e0.x * 32 + lane]);
        fma_h(a, r0, __int_as_float(e0.y));
    }
    return a;
}

// T1 = L @ T0 ; out = c0*X + c1*T1
__global__ void cheb_first_acc(const __half* __restrict__ T0h,
                               const float* __restrict__ X,
                               __half* __restrict__ T1,
                               float* __restrict__ out,
                               const float* __restrict__ coeffs) {
    int gw   = (blockIdx.x * blockDim.x + threadIdx.x) >> 5;
    int lane = threadIdx.x & 31;
    if (gw >= NN) return;
    int s = g_rptr[gw], e = g_rptr[gw + 1];

    float4 a = spmm_row_h(T0h, s, e, lane);

    int idx = gw * 32 + lane;
    ((uint2*)T1)[idx] = pack_h(a);

    float4 x0 = __ldg(&((const float4*)X)[idx]);
    float c0 = __ldg(&coeffs[0]), c1 = __ldg(&coeffs[1]);
    float4 o;
    o.x = c0 * x0.x + c1 * a.x;
    o.y = c0 * x0.y + c1 * a.y;
    o.z = c0 * x0.z + c1 * a.z;
    o.w = c0 * x0.w + c1 * a.w;
    ((float4*)out)[idx] = o;
}

// Tk = 2*(L @ Tc) - Tp  (plain; byte-identical behavior to R10)
__global__ void cheb_step(const __half* __restrict__ Tc,
                          const __half* __restrict__ Tp,
                          __half* __restrict__ Tn) {
    int gw   = (blockIdx.x * blockDim.x + threadIdx.x) >> 5;
    int lane = threadIdx.x & 31;
    if (gw >= NN) return;
    int s = g_rptr[gw], e = g_rptr[gw + 1];

    float4 a = spmm_row_h(Tc, s, e, lane);

    int idx = gw * 32 + lane;
    uint2 tpr = __ldg(&((const uint2*)Tp)[idx]);
    float2 tplo = __half22float2(*(const __half2*)&tpr.x);
    float2 tphi = __half22float2(*(const __half2*)&tpr.y);

    float4 tk;
    tk.x = 2.f * a.x - tplo.x;
    tk.y = 2.f * a.y - tplo.y;
    tk.z = 2.f * a.z - tphi.x;
    tk.w = 2.f * a.w - tphi.y;
    ((uint2*)Tn)[idx] = pack_h(tk);
}

// Step + QUAD accumulation: out += c_{k-3}*T3 + c_{k-2}*Tp + c_{k-1}*Tc + c_k*Tk.
// Tp is already loaded for the recurrence; Tc/T3/out are L2-hot streams that
// ride the latency-bound SpMM.
__global__ void cheb_step_quad(const __half* __restrict__ Tc,
                               const __half* __restrict__ Tp,
                               const __half* __restrict__ T3,
                               __half* __restrict__ Tn,
                               float* __restrict__ out,
                               const float* __restrict__ coeffs, int k) {
    int gw   = (blockIdx.x * blockDim.x + threadIdx.x) >> 5;
    int lane = threadIdx.x & 31;
    if (gw >= NN) return;
    int s = g_rptr[gw], e = g_rptr[gw + 1];

    float4 a = spmm_row_h(Tc, s, e, lane);

    int idx = gw * 32 + lane;
    uint2 tpr = __ldg(&((const uint2*)Tp)[idx]);
    float2 tplo = __half22float2(*(const __half2*)&tpr.x);
    float2 tphi = __half22float2(*(const __half2*)&tpr.y);

    float4 tk;
    tk.x = 2.f * a.x - tplo.x;
    tk.y = 2.f * a.y - tplo.y;
    tk.z = 2.f * a.z - tphi.x;
    tk.w = 2.f * a.w - tphi.y;
    ((uint2*)Tn)[idx] = pack_h(tk);

    // quad accumulate (fp32): coeffs k-3 .. k
    uint2 t3r = __ldg(&((const uint2*)T3)[idx]);
    uint2 tcr = __ldg(&((const uint2*)Tc)[idx]);
    float ck3 = __ldg(&coeffs[k - 3]);
    float ck2 = __ldg(&coeffs[k - 2]);
    float ck1 = __ldg(&coeffs[k - 1]);
    float ck  = __ldg(&coeffs[k]);

    float4 o = ((const float4*)out)[idx];
    fma_h(o, t3r, ck3);          // c_{k-3} * T_{k-3}
    fma_h(o, tpr, ck2);          // c_{k-2} * T_{k-2} (reuse recurrence load)
    fma_h(o, tcr, ck1);          // c_{k-1} * T_{k-1}
    o.x += ck * tk.x;
    o.y += ck * tk.y;
    o.z += ck * tk.z;
    o.w += ck * tk.w;
    ((float4*)out)[idx] = o;
}

// tail fixup for general M: out += c_j * Tj
__global__ void tail_acc_kernel(const __half* __restrict__ Tj,
                                const float* __restrict__ coeffs,
                                float* __restrict__ out, int j) {
    int i = blockIdx.x * blockDim.x + threadIdx.x;
    if (i >= NV2) return;
    uint2 r = __ldg(&((const uint2*)Tj)[i]);
    float4 o = ((const float4*)out)[i];
    fma_h(o, r, __ldg(&coeffs[j]));
    ((float4*)out)[i] = o;
}

// ---------------- launch ----------------
extern "C" void kernel_launch(void* const* d_in, const int* in_sizes, int n_in,
                              void* d_out, int out_size) {
    const int*   rows   = (const int*)d_in[0];
    const int*   cols   = (const int*)d_in[1];
    const float* vals   = (const float*)d_in[2];
    const float* X      = (const float*)d_in[3];
    const float* coeffs = (const float*)d_in[4];
    const int nnz = in_sizes[0];
    const int M   = in_sizes[4];

    void* p;
    __half* buf[4];
    int* pcnt;
    cudaGetSymbolAddress(&p, g_b0);  buf[0] = (__half*)p;
    cudaGetSymbolAddress(&p, g_b1);  buf[1] = (__half*)p;
    cudaGetSymbolAddress(&p, g_b2);  buf[2] = (__half*)p;
    cudaGetSymbolAddress(&p, g_b3);  buf[3] = (__half*)p;
    cudaGetSymbolAddress(&p, g_cnt); pcnt = (int*)p;

    float* outp = (float*)d_out;

    // ---- CSR build (in-graph, re-done every replay) ----
    cudaMemsetAsync(pcnt, 0, NN * sizeof(int));
    hist_kernel<<<(nnz + 255) / 256, 256>>>(rows, nnz);
    scan_blocks_kernel<<<NBLK, SCAN_BLK>>>();
    scan_totals_kernel<<<1, SCAN_BLK>>>(nnz);
    scan_fixup_kernel<<<NBLK, SCAN_BLK>>>();
    scatter_kernel<<<(nnz + 255) / 256, 256>>>(rows, cols, vals, nnz);

    // ---- X -> fp16 buffer 0 (T0) ----
    convert_kernel<<<(NV2 + 255) / 256, 256>>>(X, buf[0]);

    // ---- Chebyshev recurrence, 4 rotating buffers, quad accumulation ----
    const int threads = 256;                 // 8 rows per block
    const int rowsPerBlk = threads / 32;
    const int grid = (NN + rowsPerBlk - 1) / rowsPerBlk;

    // T1 = L T0, out = c0*X + c1*T1   (T_k lives in buf[k % 4])
    cheb_first_acc<<<grid, threads>>>(buf[0], X, buf[1], outp, coeffs);

    int last_acc = 1;   // coeffs 0..1 accumulated
    for (int k = 2; k < M; k++) {
        const __half* Tc = buf[(k - 1) & 3];
        const __half* Tp = buf[(k - 2) & 3];
        __half*       Tn = buf[k & 3];
        if (k - last_acc == 4) {   // T_{k-3..k} all alive in the 4 buffers
            const __half* T3 = buf[(k - 3) & 3];
            cheb_step_quad<<<grid, threads>>>(Tc, Tp, T3, Tn, outp, coeffs, k);
            last_acc = k;
        } else {
            cheb_step<<<grid, threads>>>(Tc, Tp, Tn);
        }
    }

    // tail: accumulate any leftover coeffs (at most 3; their T's are alive)
    for (int j = last_acc + 1; j < M; j++) {
        tail_acc_kernel<<<(NV2 + 255) / 256, 256>>>(buf[j & 3], coeffs, outp, j);
    }
}

// round 16
// speedup vs baseline: 1.1981x; 1.0028x over previous
#include <cuda_runtime.h>
#include <cuda_fp16.h>

#define NN   50000
#define DD   128
#define NV2  (NN * DD / 4)      // uint2 (4 halves) per T buffer = 1.6M
#define NNZ_CAP 800000

#define SCAN_BLK 256
#define NBLK ((NN + SCAN_BLK - 1) / SCAN_BLK)   // 196

// ---- static scratch (allocation-free rule: __device__ globals) ----
__device__ __half g_b0[NN * DD];     // rotating Chebyshev buffers (fp16): T_k -> buf[k%4]
__device__ __half g_b1[NN * DD];
__device__ __half g_b2[NN * DD];
__device__ __half g_b3[NN * DD];
__device__ int   g_cnt[NN];
__device__ int   g_rptr[NN + 1];
__device__ int   g_cursor[NN];
__device__ int   g_blksum[NBLK];
__device__ int2  g_edges[NNZ_CAP];   // {col, val-as-int}

// ---------------- fused histogram + fp32->fp16 convert ----------------
// hist blocks and convert blocks are disjoint ranges of one launch; the
// atomic-bound hist rides under the DRAM-streaming convert.
__global__ void hist_convert_kernel(const int* __restrict__ rows, int nnz,
                                    const float* __restrict__ X,
                                    __half* __restrict__ H, int histBlocks) {
    if ((int)blockIdx.x < histBlocks) {
        int i = blockIdx.x * blockDim.x + threadIdx.x;
        if (i < nnz) atomicAdd(&g_cnt[rows[i]], 1);
    } else {
        int i = (blockIdx.x - histBlocks) * blockDim.x + threadIdx.x;
        if (i < NV2) {
            float4 v = __ldg(&((const float4*)X)[i]);
            __half2 lo = __floats2half2_rn(v.x, v.y);
            __half2 hi = __floats2half2_rn(v.z, v.w);
            uint2 r;
            r.x = *(unsigned int*)&lo;
            r.y = *(unsigned int*)&hi;
            ((uint2*)H)[i] = r;
        }
    }
}

// per-block exclusive scan of g_cnt -> g_rptr (local), block total -> g_blksum
__global__ void scan_blocks_kernel() {
    __shared__ int sh[SCAN_BLK];
    const int b = blockIdx.x, t = threadIdx.x;
    const int i = b * SCAN_BLK + t;
    int v = (i < NN) ? g_cnt[i] : 0;
    sh[t] = v;
    __syncthreads();
    for (int d = 1; d < SCAN_BLK; d <<= 1) {
        int x = (t >= d) ? sh[t - d] : 0;
        __syncthreads();
        sh[t] += x;
        __syncthreads();
    }
    if (i < NN) g_rptr[i] = sh[t] - v;     // exclusive within block
    if (t == SCAN_BLK - 1) g_blksum[b] = sh[t];
}

// fused totals + fixup: each block sums g_blksum[0..b) itself (<=196 ints),
// then applies the offset. One launch instead of two.
__global__ void scan_totals_fixup_kernel(int nnz) {
    __shared__ int red[SCAN_BLK];
    const int b = blockIdx.x, t = threadIdx.x;

    int part = 0;
    for (int j = t; j < b; j += SCAN_BLK) part += g_blksum[j];
    red[t] = part;
    __syncthreads();
    for (int d = SCAN_BLK / 2; d > 0; d >>= 1) {
        if (t < d) red[t] += red[t + d];
        __syncthreads();
    }
    const int off = red[0];

    const int i = b * SCAN_BLK + t;
    if (i < NN) {
        int r = g_rptr[i] + off;
        g_rptr[i]   = r;
        g_cursor[i] = r;
    }
    if (b == NBLK - 1 && t == 0) g_rptr[NN] = nnz;
}

__global__ void scatter_kernel(const int* __restrict__ rows,
                               const int* __restrict__ cols,
                               const float* __restrict__ vals, int nnz) {
    int i = blockIdx.x * blockDim.x + threadIdx.x;
    if (i < nnz) {
        int r = rows[i];
        int p = atomicAdd(&g_cursor[r], 1);
        g_edges[p] = make_int2(cols[i], __float_as_int(vals[i]));
    }
}

// ---------------- helpers ----------------
__device__ __forceinline__ void fma_h(float4& a, uint2 r, float v) {
    float2 lo = __half22float2(*(const __half2*)&r.x);
    float2 hi = __half22float2(*(const __half2*)&r.y);
    a.x += v * lo.x; a.y += v * lo.y; a.z += v * hi.x; a.w += v * hi.y;
}

__device__ __forceinline__ uint2 pack_h(float4 t) {
    __half2 lo = __floats2half2_rn(t.x, t.y);
    __half2 hi = __floats2half2_rn(t.z, t.w);
    uint2 r;
    r.x = *(unsigned int*)&lo;
    r.y = *(unsigned int*)&hi;
    return r;
}

// SpMM for one row (R6/R10-proven form: unroll-by-4, broadcast edge loads).
// DO NOT TOUCH — five restructurings of this loop all regressed.
__device__ __forceinline__ float4 spmm_row_h(const __half* __restrict__ T,
                                             int s, int e, int lane) {
    float4 a = make_float4(0.f, 0.f, 0.f, 0.f);
    const uint2* Tv = (const uint2*)T;    // 4 halves per uint2; row stride = 32
    int i = s;
    for (; i + 3 < e; i += 4) {
        int2 e0 = __ldg(&g_edges[i]);
        int2 e1 = __ldg(&g_edges[i + 1]);
        int2 e2 = __ldg(&g_edges[i + 2]);
        int2 e3 = __ldg(&g_edges[i + 3]);
        uint2 r0 = __ldg(&Tv[e0.x * 32 + lane]);
        uint2 r1 = __ldg(&Tv[e1.x * 32 + lane]);
        uint2 r2 = __ldg(&Tv[e2.x * 32 + lane]);
        uint2 r3 = __ldg(&Tv[e3.x * 32 + lane]);
        fma_h(a, r0, __int_as_float(e0.y));
        fma_h(a, r1, __int_as_float(e1.y));
        fma_h(a, r2, __int_as_float(e2.y));
        fma_h(a, r3, __int_as_float(e3.y));
    }
    for (; i < e; i++) {
        int2 e0 = __ldg(&g_edges[i]);
        uint2 r0 = __ldg(&Tv[e0.x * 32 + lane]);
        fma_h(a, r0, __int_as_float(e0.y));
    }
    return a;
}

// T1 = L @ T0 ; out = c0*X + c1*T1
__global__ void cheb_first_acc(const __half* __restrict__ T0h,
                               const float* __restrict__ X,
                               __half* __restrict__ T1,
                               float* __restrict__ out,
                               const float* __restrict__ coeffs) {
    int gw   = (blockIdx.x * blockDim.x + threadIdx.x) >> 5;
    int lane = threadIdx.x & 31;
    if (gw >= NN) return;
    int s = g_rptr[gw], e = g_rptr[gw + 1];

    float4 a = spmm_row_h(T0h, s, e, lane);

    int idx = gw * 32 + lane;
    ((uint2*)T1)[idx] = pack_h(a);

    float4 x0 = __ldg(&((const float4*)X)[idx]);
    float c0 = __ldg(&coeffs[0]), c1 = __ldg(&coeffs[1]);
    float4 o;
    o.x = c0 * x0.x + c1 * a.x;
    o.y = c0 * x0.y + c1 * a.y;
    o.z = c0 * x0.z + c1 * a.z;
    o.w = c0 * x0.w + c1 * a.w;
    ((float4*)out)[idx] = o;
}

// Tk = 2*(L @ Tc) - Tp  (plain)
__global__ void cheb_step(const __half* __restrict__ Tc,
                          const __half* __restrict__ Tp,
                          __half* __restrict__ Tn) {
    int gw   = (blockIdx.x * blockDim.x + threadIdx.x) >> 5;
    int lane = threadIdx.x & 31;
    if (gw >= NN) return;
    int s = g_rptr[gw], e = g_rptr[gw + 1];

    float4 a = spmm_row_h(Tc, s, e, lane);

    int idx = gw * 32 + lane;
    uint2 tpr = __ldg(&((const uint2*)Tp)[idx]);
    float2 tplo = __half22float2(*(const __half2*)&tpr.x);
    float2 tphi = __half22float2(*(const __half2*)&tpr.y);

    float4 tk;
    tk.x = 2.f * a.x - tplo.x;
    tk.y = 2.f * a.y - tplo.y;
    tk.z = 2.f * a.z - tphi.x;
    tk.w = 2.f * a.w - tphi.y;
    ((uint2*)Tn)[idx] = pack_h(tk);
}

// Step + QUAD accumulation: out += c_{k-3}*T3 + c_{k-2}*Tp + c_{k-1}*Tc + c_k*Tk.
__global__ void cheb_step_quad(const __half* __restrict__ Tc,
                               const __half* __restrict__ Tp,
                               const __half* __restrict__ T3,
                               __half* __restrict__ Tn,
                               float* __restrict__ out,
                               const float* __restrict__ coeffs, int k) {
    int gw   = (blockIdx.x * blockDim.x + threadIdx.x) >> 5;
    int lane = threadIdx.x & 31;
    if (gw >= NN) return;
    int s = g_rptr[gw], e = g_rptr[gw + 1];

    float4 a = spmm_row_h(Tc, s, e, lane);

    int idx = gw * 32 + lane;
    uint2 tpr = __ldg(&((const uint2*)Tp)[idx]);
    float2 tplo = __half22float2(*(const __half2*)&tpr.x);
    float2 tphi = __half22float2(*(const __half2*)&tpr.y);

    float4 tk;
    tk.x = 2.f * a.x - tplo.x;
    tk.y = 2.f * a.y - tplo.y;
    tk.z = 2.f * a.z - tphi.x;
    tk.w = 2.f * a.w - tphi.y;
    ((uint2*)Tn)[idx] = pack_h(tk);

    // quad accumulate (fp32): coeffs k-3 .. k
    uint2 t3r = __ldg(&((const uint2*)T3)[idx]);
    uint2 tcr = __ldg(&((const uint2*)Tc)[idx]);
    float ck3 = __ldg(&coeffs[k - 3]);
    float ck2 = __ldg(&coeffs[k - 2]);
    float ck1 = __ldg(&coeffs[k - 1]);
    float ck  = __ldg(&coeffs[k]);

    float4 o = ((const float4*)out)[idx];
    fma_h(o, t3r, ck3);          // c_{k-3} * T_{k-3}
    fma_h(o, tpr, ck2);          // c_{k-2} * T_{k-2} (reuse recurrence load)
    fma_h(o, tcr, ck1);          // c_{k-1} * T_{k-1}
    o.x += ck * tk.x;
    o.y += ck * tk.y;
    o.z += ck * tk.z;
    o.w += ck * tk.w;
    ((float4*)out)[idx] = o;
}

// tail fixup for general M: out += c_j * Tj
__global__ void tail_acc_kernel(const __half* __restrict__ Tj,
                                const float* __restrict__ coeffs,
                                float* __restrict__ out, int j) {
    int i = blockIdx.x * blockDim.x + threadIdx.x;
    if (i >= NV2) return;
    uint2 r = __ldg(&((const uint2*)Tj)[i]);
    float4 o = ((const float4*)out)[i];
    fma_h(o, r, __ldg(&coeffs[j]));
    ((float4*)out)[i] = o;
}

// ---------------- launch ----------------
extern "C" void kernel_launch(void* const* d_in, const int* in_sizes, int n_in,
                              void* d_out, int out_size) {
    const int*   rows   = (const int*)d_in[0];
    const int*   cols   = (const int*)d_in[1];
    const float* vals   = (const float*)d_in[2];
    const float* X      = (const float*)d_in[3];
    const float* coeffs = (const float*)d_in[4];
    const int nnz = in_sizes[0];
    const int M   = in_sizes[4];

    void* p;
    __half* buf[4];
    int* pcnt;
    cudaGetSymbolAddress(&p, g_b0);  buf[0] = (__half*)p;
    cudaGetSymbolAddress(&p, g_b1);  buf[1] = (__half*)p;
    cudaGetSymbolAddress(&p, g_b2);  buf[2] = (__half*)p;
    cudaGetSymbolAddress(&p, g_b3);  buf[3] = (__half*)p;
    cudaGetSymbolAddress(&p, g_cnt); pcnt = (int*)p;

    float* outp = (float*)d_out;

    // ---- CSR build + convert (compressed chain) ----
    cudaMemsetAsync(pcnt, 0, NN * sizeof(int));
    const int histBlocks = (nnz + 255) / 256;
    const int convBlocks = (NV2 + 255) / 256;
    hist_convert_kernel<<<histBlocks + convBlocks, 256>>>(rows, nnz, X, buf[0],
                                                          histBlocks);
    scan_blocks_kernel<<<NBLK, SCAN_BLK>>>();
    scan_totals_fixup_kernel<<<NBLK, SCAN_BLK>>>(nnz);
    scatter_kernel<<<(nnz + 255) / 256, 256>>>(rows, cols, vals, nnz);

    // ---- Chebyshev recurrence, 4 rotating buffers, quad accumulation ----
    const int threads = 256;                 // 8 rows per block
    const int rowsPerBlk = threads / 32;
    const int grid = (NN + rowsPerBlk - 1) / rowsPerBlk;

    // T1 = L T0, out = c0*X + c1*T1   (T_k lives in buf[k % 4])
    cheb_first_acc<<<grid, threads>>>(buf[0], X, buf[1], outp, coeffs);

    int last_acc = 1;   // coeffs 0..1 accumulated
    for (int k = 2; k < M; k++) {
        const __half* Tc = buf[(k - 1) & 3];
        const __half* Tp = buf[(k - 2) & 3];
        __half*       Tn = buf[k & 3];
        if (k - last_acc == 4) {   // T_{k-3..k} all alive in the 4 buffers
            const __half* T3 = buf[(k - 3) & 3];
            cheb_step_quad<<<grid, threads>>>(Tc, Tp, T3, Tn, outp, coeffs, k);
            last_acc = k;
        } else {
            cheb_step<<<grid, threads>>>(Tc, Tp, Tn);
        }
    }

    // tail: accumulate any leftover coeffs (at most 3; their T's are alive)
    for (int j = last_acc + 1; j < M; j++) {
        tail_acc_kernel<<<(NV2 + 255) / 256, 256>>>(buf[j & 3], coeffs, outp, j);
    }
}

// round 17
// speedup vs baseline: 1.1994x; 1.0010x over previous
#include <cuda_runtime.h>
#include <cuda_fp16.h>

#define NN   50000
#define DD   128
#define NV2  (NN * DD / 4)      // uint2 (4 halves) per T buffer = 1.6M
#define NNZ_CAP 800000

#define SCAN_BLK 256
#define NBLK ((NN + SCAN_BLK - 1) / SCAN_BLK)   // 196

// ---- static scratch (allocation-free rule: __device__ globals) ----
__device__ __half g_b0[NN * DD];     // rotating Chebyshev buffers (fp16): T_k -> buf[k%4]
__device__ __half g_b1[NN * DD];
__device__ __half g_b2[NN * DD];
__device__ __half g_b3[NN * DD];
__device__ int   g_cnt[NN];
__device__ int   g_rptr[NN + 1];
__device__ int   g_cursor[NN];
__device__ int   g_blksum[NBLK];
__device__ int2  g_edges[NNZ_CAP];   // {col, val-as-int}

// ---------------- fused histogram + fp32->fp16 convert ----------------
// hist blocks: 4 edges per thread (int4 loads, 4 atomics in flight).
// convert blocks: DRAM-streaming fp32->fp16.
__global__ void hist_convert_kernel(const int* __restrict__ rows, int nnz,
                                    const float* __restrict__ X,
                                    __half* __restrict__ H, int histBlocks) {
    if ((int)blockIdx.x < histBlocks) {
        int i4 = (blockIdx.x * blockDim.x + threadIdx.x) * 4;
        if (i4 + 3 < nnz) {
            int4 r = *(const int4*)(rows + i4);
            atomicAdd(&g_cnt[r.x], 1);
            atomicAdd(&g_cnt[r.y], 1);
            atomicAdd(&g_cnt[r.z], 1);
            atomicAdd(&g_cnt[r.w], 1);
        } else {
            for (int i = i4; i < nnz; i++) atomicAdd(&g_cnt[rows[i]], 1);
        }
    } else {
        int i = (blockIdx.x - histBlocks) * blockDim.x + threadIdx.x;
        if (i < NV2) {
            float4 v = __ldg(&((const float4*)X)[i]);
            __half2 lo = __floats2half2_rn(v.x, v.y);
            __half2 hi = __floats2half2_rn(v.z, v.w);
            uint2 r;
            r.x = *(unsigned int*)&lo;
            r.y = *(unsigned int*)&hi;
            ((uint2*)H)[i] = r;
        }
    }
}

// per-block exclusive scan of g_cnt -> g_rptr (local), block total -> g_blksum
__global__ void scan_blocks_kernel() {
    __shared__ int sh[SCAN_BLK];
    const int b = blockIdx.x, t = threadIdx.x;
    const int i = b * SCAN_BLK + t;
    int v = (i < NN) ? g_cnt[i] : 0;
    sh[t] = v;
    __syncthreads();
    for (int d = 1; d < SCAN_BLK; d <<= 1) {
        int x = (t >= d) ? sh[t - d] : 0;
        __syncthreads();
        sh[t] += x;
        __syncthreads();
    }
    if (i < NN) g_rptr[i] = sh[t] - v;     // exclusive within block
    if (t == SCAN_BLK - 1) g_blksum[b] = sh[t];
}

// fused totals + fixup: each block sums g_blksum[0..b) itself (<=196 ints),
// then applies the offset.
__global__ void scan_totals_fixup_kernel(int nnz) {
    __shared__ int red[SCAN_BLK];
    const int b = blockIdx.x, t = threadIdx.x;

    int part = 0;
    for (int j = t; j < b; j += SCAN_BLK) part += g_blksum[j];
    red[t] = part;
    __syncthreads();
    for (int d = SCAN_BLK / 2; d > 0; d >>= 1) {
        if (t < d) red[t] += red[t + d];
        __syncthreads();
    }
    const int off = red[0];

    const int i = b * SCAN_BLK + t;
    if (i < NN) {
        int r = g_rptr[i] + off;
        g_rptr[i]   = r;
        g_cursor[i] = r;
    }
    if (b == NBLK - 1 && t == 0) g_rptr[NN] = nnz;
}

// scatter: 4 edges per thread -> 4 independent atomics in flight
__global__ void scatter_kernel(const int* __restrict__ rows,
                               const int* __restrict__ cols,
                               const float* __restrict__ vals, int nnz) {
    int i4 = (blockIdx.x * blockDim.x + threadIdx.x) * 4;
    if (i4 + 3 < nnz) {
        int4   r = *(const int4*)(rows + i4);
        int4   c = *(const int4*)(cols + i4);
        float4 v = *(const float4*)(vals + i4);
        int p0 = atomicAdd(&g_cursor[r.x], 1);
        int p1 = atomicAdd(&g_cursor[r.y], 1);
        int p2 = atomicAdd(&g_cursor[r.z], 1);
        int p3 = atomicAdd(&g_cursor[r.w], 1);
        g_edges[p0] = make_int2(c.x, __float_as_int(v.x));
        g_edges[p1] = make_int2(c.y, __float_as_int(v.y));
        g_edges[p2] = make_int2(c.z, __float_as_int(v.z));
        g_edges[p3] = make_int2(c.w, __float_as_int(v.w));
    } else {
        for (int i = i4; i < nnz; i++) {
            int p = atomicAdd(&g_cursor[rows[i]], 1);
            g_edges[p] = make_int2(cols[i], __float_as_int(vals[i]));
        }
    }
}

// ---------------- helpers ----------------
__device__ __forceinline__ void fma_h(float4& a, uint2 r, float v) {
    float2 lo = __half22float2(*(const __half2*)&r.x);
    float2 hi = __half22float2(*(const __half2*)&r.y);
    a.x += v * lo.x; a.y += v * lo.y; a.z += v * hi.x; a.w += v * hi.y;
}

__device__ __forceinline__ uint2 pack_h(float4 t) {
    __half2 lo = __floats2half2_rn(t.x, t.y);
    __half2 hi = __floats2half2_rn(t.z, t.w);
    uint2 r;
    r.x = *(unsigned int*)&lo;
    r.y = *(unsigned int*)&hi;
    return r;
}

// SpMM for one row (R6/R10-proven form: unroll-by-4, broadcast edge loads).
// DO NOT TOUCH — five restructurings of this loop all regressed.
__device__ __forceinline__ float4 spmm_row_h(const __half* __restrict__ T,
                                             int s, int e, int lane) {
    float4 a = make_float4(0.f, 0.f, 0.f, 0.f);
    const uint2* Tv = (const uint2*)T;    // 4 halves per uint2; row stride = 32
    int i = s;
    for (; i + 3 < e; i += 4) {
        int2 e0 = __ldg(&g_edges[i]);
        int2 e1 = __ldg(&g_edges[i + 1]);
        int2 e2 = __ldg(&g_edges[i + 2]);
        int2 e3 = __ldg(&g_edges[i + 3]);
        uint2 r0 = __ldg(&Tv[e0.x * 32 + lane]);
        uint2 r1 = __ldg(&Tv[e1.x * 32 + lane]);
        uint2 r2 = __ldg(&Tv[e2.x * 32 + lane]);
        uint2 r3 = __ldg(&Tv[e3.x * 32 + lane]);
        fma_h(a, r0, __int_as_float(e0.y));
        fma_h(a, r1, __int_as_float(e1.y));
        fma_h(a, r2, __int_as_float(e2.y));
        fma_h(a, r3, __int_as_float(e3.y));
    }
    for (; i < e; i++) {
        int2 e0 = __ldg(&g_edges[i]);
        uint2 r0 = __ldg(&Tv[e0.x * 32 + lane]);
        fma_h(a, r0, __int_as_float(e0.y));
    }
    return a;
}

// T1 = L @ T0 ; out = c0*X + c1*T1
__global__ void cheb_first_acc(const __half* __restrict__ T0h,
                               const float* __restrict__ X,
                               __half* __restrict__ T1,
                               float* __restrict__ out,
                               const float* __restrict__ coeffs) {
    int gw   = (blockIdx.x * blockDim.x + threadIdx.x) >> 5;
    int lane = threadIdx.x & 31;
    if (gw >= NN) return;
    int s = g_rptr[gw], e = g_rptr[gw + 1];

    float4 a = spmm_row_h(T0h, s, e, lane);

    int idx = gw * 32 + lane;
    ((uint2*)T1)[idx] = pack_h(a);

    float4 x0 = __ldg(&((const float4*)X)[idx]);
    float c0 = __ldg(&coeffs[0]), c1 = __ldg(&coeffs[1]);
    float4 o;
    o.x = c0 * x0.x + c1 * a.x;
    o.y = c0 * x0.y + c1 * a.y;
    o.z = c0 * x0.z + c1 * a.z;
    o.w = c0 * x0.w + c1 * a.w;
    ((float4*)out)[idx] = o;
}

// Tk = 2*(L @ Tc) - Tp  (plain)
__global__ void cheb_step(const __half* __restrict__ Tc,
                          const __half* __restrict__ Tp,
                          __half* __restrict__ Tn) {
    int gw   = (blockIdx.x * blockDim.x + threadIdx.x) >> 5;
    int lane = threadIdx.x & 31;
    if (gw >= NN) return;
    int s = g_rptr[gw], e = g_rptr[gw + 1];

    float4 a = spmm_row_h(Tc, s, e, lane);

    int idx = gw * 32 + lane;
    uint2 tpr = __ldg(&((const uint2*)Tp)[idx]);
    float2 tplo = __half22float2(*(const __half2*)&tpr.x);
    float2 tphi = __half22float2(*(const __half2*)&tpr.y);

    float4 tk;
    tk.x = 2.f * a.x - tplo.x;
    tk.y = 2.f * a.y - tplo.y;
    tk.z = 2.f * a.z - tphi.x;
    tk.w = 2.f * a.w - tphi.y;
    ((uint2*)Tn)[idx] = pack_h(tk);
}

// Step + QUAD accumulation: out += c_{k-3}*T3 + c_{k-2}*Tp + c_{k-1}*Tc + c_k*Tk.
__global__ void cheb_step_quad(const __half* __restrict__ Tc,
                               const __half* __restrict__ Tp,
                               const __half* __restrict__ T3,
                               __half* __restrict__ Tn,
                               float* __restrict__ out,
                               const float* __restrict__ coeffs, int k) {
    int gw   = (blockIdx.x * blockDim.x + threadIdx.x) >> 5;
    int lane = threadIdx.x & 31;
    if (gw >= NN) return;
    int s = g_rptr[gw], e = g_rptr[gw + 1];

    float4 a = spmm_row_h(Tc, s, e, lane);

    int idx = gw * 32 + lane;
    uint2 tpr = __ldg(&((const uint2*)Tp)[idx]);
    float2 tplo = __half22float2(*(const __half2*)&tpr.x);
    float2 tphi = __half22float2(*(const __half2*)&tpr.y);

    float4 tk;
    tk.x = 2.f * a.x - tplo.x;
    tk.y = 2.f * a.y - tplo.y;
    tk.z = 2.f * a.z - tphi.x;
    tk.w = 2.f * a.w - tphi.y;
    ((uint2*)Tn)[idx] = pack_h(tk);

    // quad accumulate (fp32): coeffs k-3 .. k
    uint2 t3r = __ldg(&((const uint2*)T3)[idx]);
    uint2 tcr = __ldg(&((const uint2*)Tc)[idx]);
    float ck3 = __ldg(&coeffs[k - 3]);
    float ck2 = __ldg(&coeffs[k - 2]);
    float ck1 = __ldg(&coeffs[k - 1]);
    float ck  = __ldg(&coeffs[k]);

    float4 o = ((const float4*)out)[idx];
    fma_h(o, t3r, ck3);          // c_{k-3} * T_{k-3}
    fma_h(o, tpr, ck2);          // c_{k-2} * T_{k-2} (reuse recurrence load)
    fma_h(o, tcr, ck1);          // c_{k-1} * T_{k-1}
    o.x += ck * tk.x;
    o.y += ck * tk.y;
    o.z += ck * tk.z;
    o.w += ck * tk.w;
    ((float4*)out)[idx] = o;
}

// tail fixup for general M: out += c_j * Tj
__global__ void tail_acc_kernel(const __half* __restrict__ Tj,
                                const float* __restrict__ coeffs,
                                float* __restrict__ out, int j) {
    int i = blockIdx.x * blockDim.x + threadIdx.x;
    if (i >= NV2) return;
    uint2 r = __ldg(&((const uint2*)Tj)[i]);
    float4 o = ((const float4*)out)[i];
    fma_h(o, r, __ldg(&coeffs[j]));
    ((float4*)out)[i] = o;
}

// ---------------- launch ----------------
extern "C" void kernel_launch(void* const* d_in, const int* in_sizes, int n_in,
                              void* d_out, int out_size) {
    const int*   rows   = (const int*)d_in[0];
    const int*   cols   = (const int*)d_in[1];
    const float* vals   = (const float*)d_in[2];
    const float* X      = (const float*)d_in[3];
    const float* coeffs = (const float*)d_in[4];
    const int nnz = in_sizes[0];
    const int M   = in_sizes[4];

    void* p;
    __half* buf[4];
    int* pcnt;
    cudaGetSymbolAddress(&p, g_b0);  buf[0] = (__half*)p;
    cudaGetSymbolAddress(&p, g_b1);  buf[1] = (__half*)p;
    cudaGetSymbolAddress(&p, g_b2);  buf[2] = (__half*)p;
    cudaGetSymbolAddress(&p, g_b3);  buf[3] = (__half*)p;
    cudaGetSymbolAddress(&p, g_cnt); pcnt = (int*)p;

    float* outp = (float*)d_out;

    // ---- CSR build + convert (compressed chain, ILP-batched atomics) ----
    cudaMemsetAsync(pcnt, 0, NN * sizeof(int));
    const int histBlocks = ((nnz + 3) / 4 + 255) / 256;
    const int convBlocks = (NV2 + 255) / 256;
    hist_convert_kernel<<<histBlocks + convBlocks, 256>>>(rows, nnz, X, buf[0],
                                                          histBlocks);
    scan_blocks_kernel<<<NBLK, SCAN_BLK>>>();
    scan_totals_fixup_kernel<<<NBLK, SCAN_BLK>>>(nnz);
    scatter_kernel<<<((nnz + 3) / 4 + 255) / 256, 256>>>(rows, cols, vals, nnz);

    // ---- Chebyshev recurrence, 4 rotating buffers, quad accumulation ----
    const int threads = 256;                 // 8 rows per block
    const int rowsPerBlk = threads / 32;
    const int grid = (NN + rowsPerBlk - 1) / rowsPerBlk;

    // T1 = L T0, out = c0*X + c1*T1   (T_k lives in buf[k % 4])
    cheb_first_acc<<<grid, threads>>>(buf[0], X, buf[1], outp, coeffs);

    int last_acc = 1;   // coeffs 0..1 accumulated
    for (int k = 2; k < M; k++) {
        const __half* Tc = buf[(k - 1) & 3];
        const __half* Tp = buf[(k - 2) & 3];
        __half*       Tn = buf[k & 3];
        if (k - last_acc == 4) {   // T_{k-3..k} all alive in the 4 buffers
            const __half* T3 = buf[(k - 3) & 3];
            cheb_step_quad<<<grid, threads>>>(Tc, Tp, T3, Tn, outp, coeffs, k);
            last_acc = k;
        } else {
            cheb_step<<<grid, threads>>>(Tc, Tp, Tn);
        }
    }

    // tail: accumulate any leftover coeffs (at most 3; their T's are alive)
    for (int j = last_acc + 1; j < M; j++) {
        tail_acc_kernel<<<(NV2 + 255) / 256, 256>>>(buf[j & 3], coeffs, outp, j);
    }
}